// round 3
// baseline (speedup 1.0000x reference)
#include <cuda_runtime.h>

// Bilinear 2x upsample, NHWC f32, 2x2-output-per-thread, edge work folded into
// the i==255 / j==255 threads (ox=511 / oy=511 are pure clamp duplicates of
// input col/row 255, which those threads already hold in registers).
// in : (8, 256, 256, 64), out: (8, 512, 512, 64)

static constexpr int IN_H  = 256;
static constexpr int IN_W  = 256;
static constexpr int OUT_H = 512;
static constexpr int OUT_W = 512;
static constexpr int CV    = 16;   // float4 vectors per pixel (C=64)

__device__ __forceinline__ float4 lerp4(float4 a, float4 b, float wb) {
    float wa = 1.0f - wb;
    float4 r;
    r.x = a.x * wa + b.x * wb;
    r.y = a.y * wa + b.y * wb;
    r.z = a.z * wa + b.z * wb;
    r.w = a.w * wa + b.w * wb;
    return r;
}

__global__ __launch_bounds__(256)
void bilerp2x_q2_kernel(const float4* __restrict__ in, float4* __restrict__ out) {
    int cvec = threadIdx.x;                      // 0..15
    int i    = blockIdx.x * 16 + threadIdx.y;    // column group, 0..255
    int j    = blockIdx.y;                       // row group, 0..255
    int b    = blockIdx.z;

    int ii = i - 1;
    int jj = j - 1;
    int x_lo = max(ii, 0);
    int x_hi = ii + 1;                           // i<=255 -> ii+1<=255, no clamp needed
    int y_lo = max(jj, 0);
    int y_hi = jj + 1;

    long in_b = (long)b * IN_H * IN_W * CV;
    const float4* r0 = in + in_b + (long)(y_lo * IN_W) * CV + cvec;
    const float4* r1 = in + in_b + (long)(y_hi * IN_W) * CV + cvec;

    float4 p00 = __ldg(r0 + (long)x_lo * CV);
    float4 p01 = __ldg(r0 + (long)x_hi * CV);
    float4 p10 = __ldg(r1 + (long)x_lo * CV);
    float4 p11 = __ldg(r1 + (long)x_hi * CV);

    // horizontal lerps: ox_a = 2i-1 -> dx=0.25 ; ox_b = 2i -> dx=0.75
    float4 ta = lerp4(p00, p01, 0.25f);
    float4 tb = lerp4(p00, p01, 0.75f);
    float4 ba = lerp4(p10, p11, 0.25f);
    float4 bb = lerp4(p10, p11, 0.75f);

    int ox_a = 2 * i - 1;
    int ox_b = 2 * i;
    int oy_a = 2 * j - 1;
    int oy_b = 2 * j;

    bool wxa = (i > 0);
    bool wya = (j > 0);
    bool ex  = (i == 255);   // also emit ox=511 (pure col-255 vertical lerp)
    bool ey  = (j == 255);   // also emit oy=511 (pure row-255 horizontal lerp)

    long out_b = (long)b * OUT_H * OUT_W * CV + cvec;

    if (wya) {  // row oy_a, dy = 0.25
        long row = out_b + (long)(oy_a * OUT_W) * CV;
        if (wxa) { __stcs(&out[row + (long)ox_a * CV], lerp4(ta, ba, 0.25f)); }
        __stcs(&out[row + (long)ox_b * CV], lerp4(tb, bb, 0.25f));
        if (ex)  { __stcs(&out[row + (long)511 * CV], lerp4(p01, p11, 0.25f)); }
    }
    {           // row oy_b, dy = 0.75
        long row = out_b + (long)(oy_b * OUT_W) * CV;
        if (wxa) { __stcs(&out[row + (long)ox_a * CV], lerp4(ta, ba, 0.75f)); }
        __stcs(&out[row + (long)ox_b * CV], lerp4(tb, bb, 0.75f));
        if (ex)  { __stcs(&out[row + (long)511 * CV], lerp4(p01, p11, 0.75f)); }
    }
    if (ey) {   // row oy=511: pure row-255 horizontal lerps (y taps both clamp to 255)
        long row = out_b + (long)511 * OUT_W * CV;
        if (wxa) { __stcs(&out[row + (long)ox_a * CV], lerp4(p10, p11, 0.25f)); }
        __stcs(&out[row + (long)ox_b * CV], lerp4(p10, p11, 0.75f));
        if (ex)  { __stcs(&out[row + (long)511 * CV], p11); }  // corner = input(255,255)
    }
}

extern "C" void kernel_launch(void* const* d_in, const int* in_sizes, int n_in,
                              void* d_out, int out_size) {
    const float4* in  = (const float4*)d_in[0];
    float4*       out = (float4*)d_out;

    dim3 block(16, 16);          // tx = cvec, ty = column group within block
    dim3 grid(16, 256, 8);       // 256 column groups, 256 row groups, 8 batches
    bilerp2x_q2_kernel<<<grid, block>>>(in, out);
}